// round 1
// baseline (speedup 1.0000x reference)
#include <cuda_runtime.h>

// ODEFunc_5488968204447: fused magnitude-net + 2x value-net forward/backward.
// B = 2097152 points, DIM=2, HM=8, HP=8, NV=2, NLV=1.
// One point per thread; weights staged in SMEM, read as uniform float4 broadcasts.

#define NPTS 2097152
#define TPB  256

// ---- smem float offsets (all multiples of 4 for float4 access) ----
#define O_MW0 0     // [8][2]   16
#define O_MB0 16    // [8]       8
#define O_MW1 24    // [8][8]   64
#define O_MB1 88    // [8]       8
#define O_MW2 96    // [4][8]   32
#define O_MB2 128   // [4]       4
#define O_PW1 132   // [2][8][2] 32
#define O_PB1 164   // [2][8]   16
#define O_PW2 180   // [2][8][8] 128
#define O_PB2 308   // [2][8]   16
#define O_PW3 324   // [2][8]   16
#define O_PB3 340   // [2]       2  (pad to 344)
#define SM_TOT 344

__device__ __forceinline__ float sigmoid_f(float x) {
    return __fdividef(1.0f, 1.0f + __expf(-x));
}
__device__ __forceinline__ float tanh_f(float x) {
    // tanh(x) = 1 - 2/(exp(2x)+1); exact limits at +-inf via MUFU rcp.
    float e = __expf(2.0f * x);
    return 1.0f - __fdividef(2.0f, e + 1.0f);
}
__device__ __forceinline__ float elu_f(float x) {
    return x > 0.0f ? x : (__expf(x) - 1.0f);
}

__device__ __forceinline__ void ld8(const float4* s4, int idx4, float w[8]) {
    float4 a = s4[idx4];
    float4 b = s4[idx4 + 1];
    w[0] = a.x; w[1] = a.y; w[2] = a.z; w[3] = a.w;
    w[4] = b.x; w[5] = b.y; w[6] = b.z; w[7] = b.w;
}
__device__ __forceinline__ float dot8(const float w[8], const float a[8], float acc) {
#pragma unroll
    for (int i = 0; i < 8; i++) acc = fmaf(w[i], a[i], acc);
    return acc;
}

__global__ __launch_bounds__(TPB) void odefunc_kernel(
    const float* __restrict__ x,
    const float* __restrict__ mW0, const float* __restrict__ mb0,
    const float* __restrict__ mW1, const float* __restrict__ mb1,
    const float* __restrict__ mW2, const float* __restrict__ mb2,
    const float* __restrict__ pW1, const float* __restrict__ pb1,
    const float* __restrict__ pW2, const float* __restrict__ pb2,
    const float* __restrict__ pW3, const float* __restrict__ pb3,
    float* __restrict__ out)
{
    __shared__ __align__(16) float s[SM_TOT];
    const int t = threadIdx.x;

    // stage all weights into SMEM
    if (t < 16)  s[O_MW0 + t] = mW0[t];
    if (t < 8)   s[O_MB0 + t] = mb0[t];
    if (t < 64)  s[O_MW1 + t] = mW1[t];
    if (t < 8)   s[O_MB1 + t] = mb1[t];
    if (t < 32)  s[O_MW2 + t] = mW2[t];
    if (t < 4)   s[O_MB2 + t] = mb2[t];
    if (t < 32)  s[O_PW1 + t] = pW1[t];
    if (t < 16)  s[O_PB1 + t] = pb1[t];
    if (t < 128) s[O_PW2 + t] = pW2[t];
    if (t < 16)  s[O_PB2 + t] = pb2[t];
    if (t < 16)  s[O_PW3 + t] = pW3[t];
    if (t < 2)   s[O_PB3 + t] = pb3[t];
    __syncthreads();

    const float4* s4 = reinterpret_cast<const float4*>(s);

    const int idx = blockIdx.x * TPB + t;
    float2 xv = reinterpret_cast<const float2*>(x)[idx];
    const float x0 = xv.x, x1 = xv.y;

    // ---------------- magnitude net ----------------
    // layer 0: elu(x @ mW0^T + mb0)
    float h[8];
#pragma unroll
    for (int o = 0; o < 4; o++) {
        float4 w = s4[(O_MW0 >> 2) + o];  // rows 2o, 2o+1
        h[2*o]   = elu_f(fmaf(w.x, x0, fmaf(w.y, x1, s[O_MB0 + 2*o])));
        h[2*o+1] = elu_f(fmaf(w.z, x0, fmaf(w.w, x1, s[O_MB0 + 2*o + 1])));
    }
    // layer 1: elu(h @ mW1^T + mb1)
    float h2[8];
#pragma unroll
    for (int o = 0; o < 8; o++) {
        float w[8];
        ld8(s4, (O_MW1 >> 2) + 2*o, w);
        h2[o] = elu_f(dot8(w, h, s[O_MB1 + o]));
    }
    // bmat = h2 @ mW2^T + mb2
    float bv[4];
#pragma unroll
    for (int j = 0; j < 4; j++) {
        float w[8];
        ld8(s4, (O_MW2 >> 2) + 2*j, w);
        bv[j] = dot8(w, h2, s[O_MB2 + j]);
    }
    const float m2   = fmaf(bv[0], bv[1], bv[2] * bv[3]);
    const float magA = fmaf(bv[0], bv[0], bv[2] * bv[2]);
    const float magD = fmaf(bv[1], bv[1], bv[3] * bv[3]);

    // ---------------- value nets (NV=2) + analytic backward ----------------
    float g0 = 0.0f, g1 = 0.0f;
#pragma unroll
    for (int v = 0; v < 2; v++) {
        // f1 = tanh(x @ pW1[v]^T + pb1[v])
        float f1[8];
#pragma unroll
        for (int o = 0; o < 4; o++) {
            float4 w = s4[(O_PW1 >> 2) + v*4 + o];  // pW1[v][2o][0..1], pW1[v][2o+1][0..1]
            f1[2*o]   = tanh_f(fmaf(w.x, x0, fmaf(w.y, x1, s[O_PB1 + v*8 + 2*o])));
            f1[2*o+1] = tanh_f(fmaf(w.z, x0, fmaf(w.w, x1, s[O_PB1 + v*8 + 2*o + 1])));
        }
        // f2 = tanh(f1 @ pW2[v,0]^T + pb2[v,0])
        float f2[8];
#pragma unroll
        for (int q = 0; q < 8; q++) {
            float w[8];
            ld8(s4, (O_PW2 >> 2) + v*16 + 2*q, w);
            f2[q] = tanh_f(dot8(w, f1, s[O_PB2 + v*8 + q]));
        }
        // f3 = sigmoid(f2 . pW3[v] + pb3[v]);  s = sigmoid(f3)
        float w3[8];
        ld8(s4, (O_PW3 >> 2) + v*2, w3);
        float z  = dot8(w3, f2, s[O_PB3 + v]);
        float f3 = sigmoid_f(z);
        float sg = sigmoid_f(f3);
        float ss = sg * (1.0f - sg);

        // backward: gq = ss*pW3[v][q]*(1-f2[q]^2); gp[p] = sum_q gq * pW2[v][q][p]
        float gp[8] = {0,0,0,0,0,0,0,0};
#pragma unroll
        for (int q = 0; q < 8; q++) {
            float gq = ss * w3[q] * (1.0f - f2[q] * f2[q]);
            float w[8];
            ld8(s4, (O_PW2 >> 2) + v*16 + 2*q, w);
#pragma unroll
            for (int p = 0; p < 8; p++) gp[p] = fmaf(gq, w[p], gp[p]);
        }
        // gi = sum_p gp[p]*(1-f1[p]^2) * pW1[v][p][i]
#pragma unroll
        for (int p = 0; p < 4; p++) {
            float4 w = s4[(O_PW1 >> 2) + v*4 + p];  // pW1[v][2p][:], pW1[v][2p+1][:]
            float t0 = gp[2*p]   * (1.0f - f1[2*p]   * f1[2*p]);
            float t1 = gp[2*p+1] * (1.0f - f1[2*p+1] * f1[2*p+1]);
            g0 = fmaf(t0, w.x, g0);
            g1 = fmaf(t0, w.y, g1);
            g0 = fmaf(t1, w.z, g0);
            g1 = fmaf(t1, w.w, g1);
        }
    }
    g0 *= 0.5f;  // mean over NV=2
    g1 *= 0.5f;

    // out0 = (b1^2+b3^2)*g0 + m2*g1 ; out1 = m2*g0 + (b2^2+b4^2)*g1
    float o0 = fmaf(magA, g0, m2 * g1);
    float o1 = fmaf(m2, g0, magD * g1);
    reinterpret_cast<float2*>(out)[idx] = make_float2(o0, o1);
}

extern "C" void kernel_launch(void* const* d_in, const int* in_sizes, int n_in,
                              void* d_out, int out_size)
{
    // inputs: 0:t 1:x 2:mW0 3:mb0 4:mW1 5:mb1 6:mW2 7:mb2
    //         8:pW1 9:pb1 10:pW2 11:pb2 12:pW3 13:pb3
    const float* x   = (const float*)d_in[1];
    const float* mW0 = (const float*)d_in[2];
    const float* mb0 = (const float*)d_in[3];
    const float* mW1 = (const float*)d_in[4];
    const float* mb1 = (const float*)d_in[5];
    const float* mW2 = (const float*)d_in[6];
    const float* mb2 = (const float*)d_in[7];
    const float* pW1 = (const float*)d_in[8];
    const float* pb1 = (const float*)d_in[9];
    const float* pW2 = (const float*)d_in[10];
    const float* pb2 = (const float*)d_in[11];
    const float* pW3 = (const float*)d_in[12];
    const float* pb3 = (const float*)d_in[13];
    float* out = (float*)d_out;

    const int nblocks = NPTS / TPB;  // 8192
    odefunc_kernel<<<nblocks, TPB>>>(x, mW0, mb0, mW1, mb1, mW2, mb2,
                                     pW1, pb1, pW2, pb2, pW3, pb3, out);
}

// round 2
// speedup vs baseline: 2.7453x; 2.7453x over previous
#include <cuda_runtime.h>

// ODEFunc_5488968204447 — packed f32x2 version: 2 points per thread.
// All per-point scalars live lane-wise in 64-bit packed fp32 pairs; FMAs use
// PTX fma.rn.f32x2 (SASS FFMA2). Weights are duplicated in SMEM so one shared
// load yields a broadcast-packed (w,w) operand.

#define NPTS 2097152
#define TPB  128

typedef unsigned long long u64;

// ---- original (un-duplicated) float offsets; packed element i lives at u64 index i ----
#define O_MW0 0     // [8][2]   16
#define O_MB0 16    // [8]       8
#define O_MW1 24    // [8][8]   64
#define O_MB1 88    // [8]       8
#define O_MW2 96    // [4][8]   32
#define O_MB2 128   // [4]       4
#define O_PW1 132   // [2][8][2] 32
#define O_PB1 164   // [2][8]   16
#define O_PW2 180   // [2][8][8] 128
#define O_PB2 308   // [2][8]   16
#define O_PW3 324   // [2][8]   16
#define O_PB3 340   // [2]       2
#define SM_N  344   // floats (un-duplicated); dup smem = 2*SM_N floats

__device__ __forceinline__ u64 pack2(float lo, float hi) {
    u64 r; asm("mov.b64 %0, {%1, %2};" : "=l"(r) : "f"(lo), "f"(hi)); return r;
}
__device__ __forceinline__ void unpack2(u64 v, float& lo, float& hi) {
    asm("mov.b64 {%0, %1}, %2;" : "=f"(lo), "=f"(hi) : "l"(v));
}
__device__ __forceinline__ u64 fma2(u64 a, u64 b, u64 c) {
    u64 d; asm("fma.rn.f32x2 %0, %1, %2, %3;" : "=l"(d) : "l"(a), "l"(b), "l"(c)); return d;
}
__device__ __forceinline__ u64 mul2(u64 a, u64 b) {
    u64 d; asm("mul.rn.f32x2 %0, %1, %2;" : "=l"(d) : "l"(a), "l"(b)); return d;
}
__device__ __forceinline__ float tanhfast(float x) {
    float y; asm("tanh.approx.f32 %0, %1;" : "=f"(y) : "f"(x)); return y;
}
__device__ __forceinline__ float sigf(float x) {           // sigmoid via HW tanh
    return fmaf(0.5f, tanhfast(0.5f * x), 0.5f);
}
__device__ __forceinline__ u64 tanh2(u64 a) {
    float lo, hi; unpack2(a, lo, hi);
    return pack2(tanhfast(lo), tanhfast(hi));
}
__device__ __forceinline__ u64 elu2(u64 a) {
    float lo, hi; unpack2(a, lo, hi);
    float elo = __expf(lo) - 1.0f, ehi = __expf(hi) - 1.0f;
    lo = lo > 0.0f ? lo : elo;
    hi = hi > 0.0f ? hi : ehi;
    return pack2(lo, hi);
}
// load 8 packed weights (one 8-wide row) as 4x LDS.128
__device__ __forceinline__ void ld8p(const ulonglong2* p2, int i2, u64 w[8]) {
    ulonglong2 a = p2[i2], b = p2[i2 + 1], c = p2[i2 + 2], d = p2[i2 + 3];
    w[0] = a.x; w[1] = a.y; w[2] = b.x; w[3] = b.y;
    w[4] = c.x; w[5] = c.y; w[6] = d.x; w[7] = d.y;
}
__device__ __forceinline__ u64 dot8p(const u64 w[8], const u64 a[8], u64 acc) {
#pragma unroll
    for (int i = 0; i < 8; i++) acc = fma2(w[i], a[i], acc);
    return acc;
}

__global__ __launch_bounds__(TPB, 4) void odefunc_kernel(
    const float* __restrict__ x,
    const float* __restrict__ mW0, const float* __restrict__ mb0,
    const float* __restrict__ mW1, const float* __restrict__ mb1,
    const float* __restrict__ mW2, const float* __restrict__ mb2,
    const float* __restrict__ pW1, const float* __restrict__ pb1,
    const float* __restrict__ pW2, const float* __restrict__ pb2,
    const float* __restrict__ pW3, const float* __restrict__ pb3,
    float* __restrict__ out)
{
    __shared__ __align__(16) float s[2 * SM_N];
    const int t = threadIdx.x;

    // stage weights duplicated: packed element i = (w[i], w[i])
#define STAGE(off, src, n) \
    for (int i = t; i < (n); i += TPB) { float v = (src)[i]; s[2*((off)+i)] = v; s[2*((off)+i)+1] = v; }
    STAGE(O_MW0, mW0, 16)  STAGE(O_MB0, mb0, 8)
    STAGE(O_MW1, mW1, 64)  STAGE(O_MB1, mb1, 8)
    STAGE(O_MW2, mW2, 32)  STAGE(O_MB2, mb2, 4)
    STAGE(O_PW1, pW1, 32)  STAGE(O_PB1, pb1, 16)
    STAGE(O_PW2, pW2, 128) STAGE(O_PB2, pb2, 16)
    STAGE(O_PW3, pW3, 16)  STAGE(O_PB3, pb3, 2)
#undef STAGE
    __syncthreads();

    const u64*       S2  = reinterpret_cast<const u64*>(s);
    const ulonglong2* Sv = reinterpret_cast<const ulonglong2*>(s);

    const int gid = blockIdx.x * TPB + t;      // handles points 2*gid, 2*gid+1
    float4 xv = reinterpret_cast<const float4*>(x)[gid];
    const u64 X0 = pack2(xv.x, xv.z);          // x0 of (ptA, ptB)
    const u64 X1 = pack2(xv.y, xv.w);          // x1 of (ptA, ptB)
    const u64 NEG1 = pack2(-1.0f, -1.0f);

    // ---------------- magnitude net ----------------
    u64 h[8];
#pragma unroll
    for (int o = 0; o < 8; o++) {
        ulonglong2 w = Sv[(O_MW0 + 2 * o) >> 1];   // (w[o][0], w[o][1]) packed-dup
        h[o] = elu2(fma2(w.x, X0, fma2(w.y, X1, S2[O_MB0 + o])));
    }
    u64 h2[8];
#pragma unroll
    for (int o = 0; o < 8; o++) {
        u64 w[8]; ld8p(Sv, (O_MW1 + 8 * o) >> 1, w);
        h2[o] = elu2(dot8p(w, h, S2[O_MB1 + o]));
    }
    u64 bv[4];
#pragma unroll
    for (int j = 0; j < 4; j++) {
        u64 w[8]; ld8p(Sv, (O_MW2 + 8 * j) >> 1, w);
        bv[j] = dot8p(w, h2, S2[O_MB2 + j]);
    }
    const u64 m2   = fma2(bv[0], bv[1], mul2(bv[2], bv[3]));
    const u64 magA = fma2(bv[0], bv[0], mul2(bv[2], bv[2]));
    const u64 magD = fma2(bv[1], bv[1], mul2(bv[3], bv[3]));

    // ---------------- value nets (NV=2), fused fwd+bwd ----------------
    u64 g0 = pack2(0.0f, 0.0f), g1 = g0;
#pragma unroll
    for (int v = 0; v < 2; v++) {
        // f1 = tanh(x @ pW1[v]^T + pb1[v])
        u64 f1[8];
#pragma unroll
        for (int o = 0; o < 8; o++) {
            ulonglong2 w = Sv[(O_PW1 + v * 16 + 2 * o) >> 1];
            f1[o] = tanh2(fma2(w.x, X0, fma2(w.y, X1, S2[O_PB1 + v * 8 + o])));
        }
        // fused: z = w3.f2 + pb3 ;  gp[p] = sum_q w3[q]*(f2q^2-1)*W2[q][p]
        u64 z = S2[O_PB3 + v];
        u64 gp[8];
#pragma unroll
        for (int p = 0; p < 8; p++) gp[p] = pack2(0.0f, 0.0f);
#pragma unroll
        for (int q = 0; q < 8; q++) {
            u64 w[8]; ld8p(Sv, (O_PW2 + v * 64 + 8 * q) >> 1, w);
            u64 f2  = tanh2(dot8p(w, f1, S2[O_PB2 + v * 8 + q]));
            u64 w3q = S2[O_PW3 + v * 8 + q];
            z = fma2(w3q, f2, z);
            u64 gq = mul2(w3q, fma2(f2, f2, NEG1));   // w3q*(f2^2-1)
#pragma unroll
            for (int p = 0; p < 8; p++) gp[p] = fma2(gq, w[p], gp[p]);
        }
        // ss = sig(sig(z))*(1-sig(sig(z))) * 0.5 (mean over NV folded in)
        float zl, zh; unpack2(z, zl, zh);
        float f3l = sigf(zl), f3h = sigf(zh);
        float sl = sigf(f3l), sh = sigf(f3h);
        u64 ssp = pack2(sl * (1.0f - sl) * 0.5f, sh * (1.0f - sh) * 0.5f);

        // gv = sum_p gp[p]*(f1p^2-1)*pW1[v][p][:]   (two sign flips cancel)
        u64 gv0 = pack2(0.0f, 0.0f), gv1 = gv0;
#pragma unroll
        for (int p = 0; p < 8; p++) {
            u64 tp = mul2(gp[p], fma2(f1[p], f1[p], NEG1));
            ulonglong2 w = Sv[(O_PW1 + v * 16 + 2 * p) >> 1];
            gv0 = fma2(tp, w.x, gv0);
            gv1 = fma2(tp, w.y, gv1);
        }
        g0 = fma2(gv0, ssp, g0);
        g1 = fma2(gv1, ssp, g1);
    }

    // out0 = magA*g0 + m2*g1 ; out1 = m2*g0 + magD*g1
    u64 o0 = fma2(magA, g0, mul2(m2, g1));
    u64 o1 = fma2(m2, g0, mul2(magD, g1));
    float o0l, o0h, o1l, o1h;
    unpack2(o0, o0l, o0h);
    unpack2(o1, o1l, o1h);
    reinterpret_cast<float4*>(out)[gid] = make_float4(o0l, o1l, o0h, o1h);
}

extern "C" void kernel_launch(void* const* d_in, const int* in_sizes, int n_in,
                              void* d_out, int out_size)
{
    // inputs: 0:t 1:x 2:mW0 3:mb0 4:mW1 5:mb1 6:mW2 7:mb2
    //         8:pW1 9:pb1 10:pW2 11:pb2 12:pW3 13:pb3
    const float* x   = (const float*)d_in[1];
    const float* mW0 = (const float*)d_in[2];
    const float* mb0 = (const float*)d_in[3];
    const float* mW1 = (const float*)d_in[4];
    const float* mb1 = (const float*)d_in[5];
    const float* mW2 = (const float*)d_in[6];
    const float* mb2 = (const float*)d_in[7];
    const float* pW1 = (const float*)d_in[8];
    const float* pb1 = (const float*)d_in[9];
    const float* pW2 = (const float*)d_in[10];
    const float* pb2 = (const float*)d_in[11];
    const float* pW3 = (const float*)d_in[12];
    const float* pb3 = (const float*)d_in[13];
    float* out = (float*)d_out;

    const int nblocks = NPTS / 2 / TPB;   // 8192
    odefunc_kernel<<<nblocks, TPB>>>(x, mW0, mb0, mW1, mb1, mW2, mb2,
                                     pW1, pb1, pW2, pb2, pW3, pb3, out);
}

// round 3
// speedup vs baseline: 2.8252x; 1.0291x over previous
#include <cuda_runtime.h>

// ODEFunc_5488968204447 — 4 points/thread as two packed f32x2 pairs.
// Each SMEM weight load is reused for both pairs (halves LDS per point vs R2).

#define NPTS 2097152
#define TPB  128

typedef unsigned long long u64;

// ---- un-duplicated float offsets; packed (dup) element i is u64 index i ----
#define O_MW0 0
#define O_MB0 16
#define O_MW1 24
#define O_MB1 88
#define O_MW2 96
#define O_MB2 128
#define O_PW1 132
#define O_PB1 164
#define O_PW2 180
#define O_PB2 308
#define O_PW3 324
#define O_PB3 340
#define SM_N  344

__device__ __forceinline__ u64 pack2(float lo, float hi) {
    u64 r; asm("mov.b64 %0, {%1, %2};" : "=l"(r) : "f"(lo), "f"(hi)); return r;
}
__device__ __forceinline__ void unpack2(u64 v, float& lo, float& hi) {
    asm("mov.b64 {%0, %1}, %2;" : "=f"(lo), "=f"(hi) : "l"(v));
}
__device__ __forceinline__ u64 fma2(u64 a, u64 b, u64 c) {
    u64 d; asm("fma.rn.f32x2 %0, %1, %2, %3;" : "=l"(d) : "l"(a), "l"(b), "l"(c)); return d;
}
__device__ __forceinline__ u64 mul2(u64 a, u64 b) {
    u64 d; asm("mul.rn.f32x2 %0, %1, %2;" : "=l"(d) : "l"(a), "l"(b)); return d;
}
__device__ __forceinline__ float tanhfast(float x) {
    float y; asm("tanh.approx.f32 %0, %1;" : "=f"(y) : "f"(x)); return y;
}
__device__ __forceinline__ float sigf(float x) {
    return fmaf(0.5f, tanhfast(0.5f * x), 0.5f);
}
__device__ __forceinline__ u64 tanh2(u64 a) {
    float lo, hi; unpack2(a, lo, hi);
    return pack2(tanhfast(lo), tanhfast(hi));
}
__device__ __forceinline__ u64 elu2(u64 a) {
    float lo, hi; unpack2(a, lo, hi);
    float elo = __expf(lo) - 1.0f, ehi = __expf(hi) - 1.0f;
    lo = lo > 0.0f ? lo : elo;
    hi = hi > 0.0f ? hi : ehi;
    return pack2(lo, hi);
}
__device__ __forceinline__ void ld8p(const ulonglong2* p2, int i2, u64 w[8]) {
    ulonglong2 a = p2[i2], b = p2[i2 + 1], c = p2[i2 + 2], d = p2[i2 + 3];
    w[0] = a.x; w[1] = a.y; w[2] = b.x; w[3] = b.y;
    w[4] = c.x; w[5] = c.y; w[6] = d.x; w[7] = d.y;
}

__global__ __launch_bounds__(TPB, 3) void odefunc_kernel(
    const float* __restrict__ x,
    const float* __restrict__ mW0, const float* __restrict__ mb0,
    const float* __restrict__ mW1, const float* __restrict__ mb1,
    const float* __restrict__ mW2, const float* __restrict__ mb2,
    const float* __restrict__ pW1, const float* __restrict__ pb1,
    const float* __restrict__ pW2, const float* __restrict__ pb2,
    const float* __restrict__ pW3, const float* __restrict__ pb3,
    float* __restrict__ out)
{
    __shared__ __align__(16) float s[2 * SM_N];
    const int t = threadIdx.x;

#define STAGE(off, src, n) \
    for (int i = t; i < (n); i += TPB) { float v = (src)[i]; s[2*((off)+i)] = v; s[2*((off)+i)+1] = v; }
    STAGE(O_MW0, mW0, 16)  STAGE(O_MB0, mb0, 8)
    STAGE(O_MW1, mW1, 64)  STAGE(O_MB1, mb1, 8)
    STAGE(O_MW2, mW2, 32)  STAGE(O_MB2, mb2, 4)
    STAGE(O_PW1, pW1, 32)  STAGE(O_PB1, pb1, 16)
    STAGE(O_PW2, pW2, 128) STAGE(O_PB2, pb2, 16)
    STAGE(O_PW3, pW3, 16)  STAGE(O_PB3, pb3, 2)
#undef STAGE
    __syncthreads();

    const u64*        S2 = reinterpret_cast<const u64*>(s);
    const ulonglong2* Sv = reinterpret_cast<const ulonglong2*>(s);

    // pair 0: float4 index blk*256 + t ; pair 1: blk*256 + 128 + t  (both coalesced)
    const int base = blockIdx.x * (2 * TPB) + t;
    u64 X0[2], X1[2];
#pragma unroll
    for (int j = 0; j < 2; j++) {
        float4 xv = reinterpret_cast<const float4*>(x)[base + j * TPB];
        X0[j] = pack2(xv.x, xv.z);
        X1[j] = pack2(xv.y, xv.w);
    }
    const u64 NEG1 = pack2(-1.0f, -1.0f);
    const u64 ZERO = pack2(0.0f, 0.0f);

    // ---------------- magnitude net ----------------
    u64 h[2][8];
#pragma unroll
    for (int o = 0; o < 8; o++) {
        ulonglong2 w = Sv[(O_MW0 + 2 * o) >> 1];
        u64 b = S2[O_MB0 + o];
#pragma unroll
        for (int j = 0; j < 2; j++)
            h[j][o] = elu2(fma2(w.x, X0[j], fma2(w.y, X1[j], b)));
    }
    u64 h2[2][8];
#pragma unroll
    for (int o = 0; o < 8; o++) {
        u64 w[8]; ld8p(Sv, (O_MW1 + 8 * o) >> 1, w);
        u64 b = S2[O_MB1 + o];
#pragma unroll
        for (int j = 0; j < 2; j++) {
            u64 acc = b;
#pragma unroll
            for (int i = 0; i < 8; i++) acc = fma2(w[i], h[j][i], acc);
            h2[j][o] = elu2(acc);
        }
    }
    u64 bv[2][4];
#pragma unroll
    for (int o = 0; o < 4; o++) {
        u64 w[8]; ld8p(Sv, (O_MW2 + 8 * o) >> 1, w);
        u64 b = S2[O_MB2 + o];
#pragma unroll
        for (int j = 0; j < 2; j++) {
            u64 acc = b;
#pragma unroll
            for (int i = 0; i < 8; i++) acc = fma2(w[i], h2[j][i], acc);
            bv[j][o] = acc;
        }
    }
    u64 m2[2], magA[2], magD[2];
#pragma unroll
    for (int j = 0; j < 2; j++) {
        m2[j]   = fma2(bv[j][0], bv[j][1], mul2(bv[j][2], bv[j][3]));
        magA[j] = fma2(bv[j][0], bv[j][0], mul2(bv[j][2], bv[j][2]));
        magD[j] = fma2(bv[j][1], bv[j][1], mul2(bv[j][3], bv[j][3]));
    }

    // ---------------- value nets (NV=2), fused fwd+bwd ----------------
    u64 g0[2] = {ZERO, ZERO}, g1[2] = {ZERO, ZERO};
#pragma unroll
    for (int v = 0; v < 2; v++) {
        u64 f1[2][8];
#pragma unroll
        for (int o = 0; o < 8; o++) {
            ulonglong2 w = Sv[(O_PW1 + v * 16 + 2 * o) >> 1];
            u64 b = S2[O_PB1 + v * 8 + o];
#pragma unroll
            for (int j = 0; j < 2; j++)
                f1[j][o] = tanh2(fma2(w.x, X0[j], fma2(w.y, X1[j], b)));
        }
        u64 z[2] = {S2[O_PB3 + v], S2[O_PB3 + v]};
        u64 gp[2][8];
#pragma unroll
        for (int p = 0; p < 8; p++) { gp[0][p] = ZERO; gp[1][p] = ZERO; }
#pragma unroll
        for (int q = 0; q < 8; q++) {
            u64 w[8]; ld8p(Sv, (O_PW2 + v * 64 + 8 * q) >> 1, w);
            u64 b   = S2[O_PB2 + v * 8 + q];
            u64 w3q = S2[O_PW3 + v * 8 + q];
#pragma unroll
            for (int j = 0; j < 2; j++) {
                u64 acc = b;
#pragma unroll
                for (int i = 0; i < 8; i++) acc = fma2(w[i], f1[j][i], acc);
                u64 f2 = tanh2(acc);
                z[j] = fma2(w3q, f2, z[j]);
                u64 gq = mul2(w3q, fma2(f2, f2, NEG1));   // w3q*(f2^2-1)
#pragma unroll
                for (int p = 0; p < 8; p++) gp[j][p] = fma2(gq, w[p], gp[j][p]);
            }
        }
        u64 ssp[2];
#pragma unroll
        for (int j = 0; j < 2; j++) {
            float zl, zh; unpack2(z[j], zl, zh);
            float f3l = sigf(zl), f3h = sigf(zh);
            float sl = sigf(f3l), sh = sigf(f3h);
            ssp[j] = pack2(sl * (1.0f - sl) * 0.5f, sh * (1.0f - sh) * 0.5f);
        }
        u64 gv0[2] = {ZERO, ZERO}, gv1[2] = {ZERO, ZERO};
#pragma unroll
        for (int p = 0; p < 8; p++) {
            ulonglong2 w = Sv[(O_PW1 + v * 16 + 2 * p) >> 1];
#pragma unroll
            for (int j = 0; j < 2; j++) {
                u64 tp = mul2(gp[j][p], fma2(f1[j][p], f1[j][p], NEG1));
                gv0[j] = fma2(tp, w.x, gv0[j]);
                gv1[j] = fma2(tp, w.y, gv1[j]);
            }
        }
#pragma unroll
        for (int j = 0; j < 2; j++) {
            g0[j] = fma2(gv0[j], ssp[j], g0[j]);
            g1[j] = fma2(gv1[j], ssp[j], g1[j]);
        }
    }

#pragma unroll
    for (int j = 0; j < 2; j++) {
        u64 o0 = fma2(magA[j], g0[j], mul2(m2[j], g1[j]));
        u64 o1 = fma2(m2[j], g0[j], mul2(magD[j], g1[j]));
        float o0l, o0h, o1l, o1h;
        unpack2(o0, o0l, o0h);
        unpack2(o1, o1l, o1h);
        reinterpret_cast<float4*>(out)[base + j * TPB] = make_float4(o0l, o1l, o0h, o1h);
    }
}

extern "C" void kernel_launch(void* const* d_in, const int* in_sizes, int n_in,
                              void* d_out, int out_size)
{
    const float* x   = (const float*)d_in[1];
    const float* mW0 = (const float*)d_in[2];
    const float* mb0 = (const float*)d_in[3];
    const float* mW1 = (const float*)d_in[4];
    const float* mb1 = (const float*)d_in[5];
    const float* mW2 = (const float*)d_in[6];
    const float* mb2 = (const float*)d_in[7];
    const float* pW1 = (const float*)d_in[8];
    const float* pb1 = (const float*)d_in[9];
    const float* pW2 = (const float*)d_in[10];
    const float* pb2 = (const float*)d_in[11];
    const float* pW3 = (const float*)d_in[12];
    const float* pb3 = (const float*)d_in[13];
    float* out = (float*)d_out;

    const int nblocks = NPTS / 4 / TPB;   // 4096
    odefunc_kernel<<<nblocks, TPB>>>(x, mW0, mb0, mW1, mb1, mW2, mb2,
                                     pW1, pb1, pW2, pb2, pW3, pb3, out);
}

// round 4
// speedup vs baseline: 3.0613x; 1.0835x over previous
#include <cuda_runtime.h>

// ODEFunc_5488968204447 — R4: weights in __constant__ (dup-packed f32x2),
// 2 points/thread, packed FFMA2 math, zero shared memory in the main kernel.
// Prep kernel + cudaMemcpyToSymbolAsync (D2D) stage the constant bank each call.

#define NPTS 2097152
#define TPB  128

typedef unsigned long long u64;

// ---- float offsets into the logical weight blob; u64 (dup) index == float index ----
#define O_MW0 0     // [8][2]   16
#define O_MB0 16    // [8]       8
#define O_MW1 24    // [8][8]   64
#define O_MB1 88    // [8]       8
#define O_MW2 96    // [4][8]   32
#define O_MB2 128   // [4]       4
#define O_PW1 132   // [2][8][2] 32
#define O_PB1 164   // [2][8]   16
#define O_PW2 180   // [2][8][8] 128
#define O_PB2 308   // [2][8]   16
#define O_PW3 324   // [2][8]   16
#define O_PB3 340   // [2]       2
#define SM_N  344

__constant__ u64 cw2[SM_N];          // packed-dup weights: element i = (w[i], w[i])
__device__  u64 g_stage[SM_N];       // staging buffer written by prep kernel

__device__ __forceinline__ u64 pack2(float lo, float hi) {
    u64 r; asm("mov.b64 %0, {%1, %2};" : "=l"(r) : "f"(lo), "f"(hi)); return r;
}
__device__ __forceinline__ void unpack2(u64 v, float& lo, float& hi) {
    asm("mov.b64 {%0, %1}, %2;" : "=f"(lo), "=f"(hi) : "l"(v));
}
__device__ __forceinline__ u64 fma2(u64 a, u64 b, u64 c) {
    u64 d; asm("fma.rn.f32x2 %0, %1, %2, %3;" : "=l"(d) : "l"(a), "l"(b), "l"(c)); return d;
}
__device__ __forceinline__ u64 mul2(u64 a, u64 b) {
    u64 d; asm("mul.rn.f32x2 %0, %1, %2;" : "=l"(d) : "l"(a), "l"(b)); return d;
}
__device__ __forceinline__ float tanhfast(float x) {
    float y; asm("tanh.approx.f32 %0, %1;" : "=f"(y) : "f"(x)); return y;
}
__device__ __forceinline__ float sigf(float x) {
    return fmaf(0.5f, tanhfast(0.5f * x), 0.5f);
}
__device__ __forceinline__ u64 tanh2(u64 a) {
    float lo, hi; unpack2(a, lo, hi);
    return pack2(tanhfast(lo), tanhfast(hi));
}
__device__ __forceinline__ u64 elu2(u64 a) {
    float lo, hi; unpack2(a, lo, hi);
    float elo = __expf(lo) - 1.0f, ehi = __expf(hi) - 1.0f;
    lo = lo > 0.0f ? lo : elo;
    hi = hi > 0.0f ? hi : ehi;
    return pack2(lo, hi);
}

// ---------------- prep: gather 13 arrays -> dup-packed staging blob ----------------
__global__ void prep_kernel(
    const float* __restrict__ mW0, const float* __restrict__ mb0,
    const float* __restrict__ mW1, const float* __restrict__ mb1,
    const float* __restrict__ mW2, const float* __restrict__ mb2,
    const float* __restrict__ pW1, const float* __restrict__ pb1,
    const float* __restrict__ pW2, const float* __restrict__ pb2,
    const float* __restrict__ pW3, const float* __restrict__ pb3)
{
    int i = threadIdx.x;
    if (i >= SM_N) return;
    float v;
    if      (i < O_MB0) v = mW0[i - O_MW0];
    else if (i < O_MW1) v = mb0[i - O_MB0];
    else if (i < O_MB1) v = mW1[i - O_MW1];
    else if (i < O_MW2) v = mb1[i - O_MB1];
    else if (i < O_MB2) v = mW2[i - O_MW2];
    else if (i < O_PW1) v = mb2[i - O_MB2];
    else if (i < O_PB1) v = pW1[i - O_PW1];
    else if (i < O_PW2) v = pb1[i - O_PB1];
    else if (i < O_PB2) v = pW2[i - O_PW2];
    else if (i < O_PW3) v = pb2[i - O_PB2];
    else if (i < O_PB3) v = pW3[i - O_PW3];
    else                v = pb3[i - O_PB3];
    g_stage[i] = pack2(v, v);
}

// ---------------- main: 2 points per thread ----------------
__global__ __launch_bounds__(TPB, 5) void odefunc_kernel(
    const float* __restrict__ x, float* __restrict__ out)
{
    const int gid = blockIdx.x * TPB + threadIdx.x;   // points 2*gid, 2*gid+1
    float4 xv = reinterpret_cast<const float4*>(x)[gid];
    const u64 X0 = pack2(xv.x, xv.z);
    const u64 X1 = pack2(xv.y, xv.w);
    const u64 NEG1 = pack2(-1.0f, -1.0f);
    const u64 ZERO = pack2(0.0f, 0.0f);

    // ---------------- value nets first (frees X-adjacent state early) ----------------
    u64 g0 = ZERO, g1 = ZERO;
#pragma unroll
    for (int v = 0; v < 2; v++) {
        u64 f1[8];
#pragma unroll
        for (int o = 0; o < 8; o++) {
            u64 w0 = cw2[O_PW1 + v * 16 + 2 * o];
            u64 w1 = cw2[O_PW1 + v * 16 + 2 * o + 1];
            f1[o] = tanh2(fma2(w0, X0, fma2(w1, X1, cw2[O_PB1 + v * 8 + o])));
        }
        u64 z = cw2[O_PB3 + v];
        u64 gp[8];
#pragma unroll
        for (int p = 0; p < 8; p++) gp[p] = ZERO;
#pragma unroll
        for (int q = 0; q < 8; q++) {
            u64 acc = cw2[O_PB2 + v * 8 + q];
#pragma unroll
            for (int i = 0; i < 8; i++)
                acc = fma2(cw2[O_PW2 + v * 64 + 8 * q + i], f1[i], acc);
            u64 f2  = tanh2(acc);
            u64 w3q = cw2[O_PW3 + v * 8 + q];
            z = fma2(w3q, f2, z);
            u64 gq = mul2(w3q, fma2(f2, f2, NEG1));     // w3q*(f2^2-1)
#pragma unroll
            for (int p = 0; p < 8; p++)
                gp[p] = fma2(gq, cw2[O_PW2 + v * 64 + 8 * q + p], gp[p]);
        }
        float zl, zh; unpack2(z, zl, zh);
        float f3l = sigf(zl), f3h = sigf(zh);
        float sl = sigf(f3l), sh = sigf(f3h);
        u64 ssp = pack2(sl * (1.0f - sl) * 0.5f, sh * (1.0f - sh) * 0.5f);

        u64 gv0 = ZERO, gv1 = ZERO;
#pragma unroll
        for (int p = 0; p < 8; p++) {
            u64 tp = mul2(gp[p], fma2(f1[p], f1[p], NEG1));  // sign flips cancel
            gv0 = fma2(tp, cw2[O_PW1 + v * 16 + 2 * p],     gv0);
            gv1 = fma2(tp, cw2[O_PW1 + v * 16 + 2 * p + 1], gv1);
        }
        g0 = fma2(gv0, ssp, g0);
        g1 = fma2(gv1, ssp, g1);
    }

    // ---------------- magnitude net ----------------
    u64 h[8];
#pragma unroll
    for (int o = 0; o < 8; o++) {
        u64 w0 = cw2[O_MW0 + 2 * o];
        u64 w1 = cw2[O_MW0 + 2 * o + 1];
        h[o] = elu2(fma2(w0, X0, fma2(w1, X1, cw2[O_MB0 + o])));
    }
    u64 h2[8];
#pragma unroll
    for (int o = 0; o < 8; o++) {
        u64 acc = cw2[O_MB1 + o];
#pragma unroll
        for (int i = 0; i < 8; i++)
            acc = fma2(cw2[O_MW1 + 8 * o + i], h[i], acc);
        h2[o] = elu2(acc);
    }
    u64 bv[4];
#pragma unroll
    for (int j = 0; j < 4; j++) {
        u64 acc = cw2[O_MB2 + j];
#pragma unroll
        for (int i = 0; i < 8; i++)
            acc = fma2(cw2[O_MW2 + 8 * j + i], h2[i], acc);
        bv[j] = acc;
    }
    const u64 m2   = fma2(bv[0], bv[1], mul2(bv[2], bv[3]));
    const u64 magA = fma2(bv[0], bv[0], mul2(bv[2], bv[2]));
    const u64 magD = fma2(bv[1], bv[1], mul2(bv[3], bv[3]));

    u64 o0 = fma2(magA, g0, mul2(m2, g1));
    u64 o1 = fma2(m2, g0, mul2(magD, g1));
    float o0l, o0h, o1l, o1h;
    unpack2(o0, o0l, o0h);
    unpack2(o1, o1l, o1h);
    reinterpret_cast<float4*>(out)[gid] = make_float4(o0l, o1l, o0h, o1h);
}

extern "C" void kernel_launch(void* const* d_in, const int* in_sizes, int n_in,
                              void* d_out, int out_size)
{
    // inputs: 0:t 1:x 2:mW0 3:mb0 4:mW1 5:mb1 6:mW2 7:mb2
    //         8:pW1 9:pb1 10:pW2 11:pb2 12:pW3 13:pb3
    const float* x   = (const float*)d_in[1];
    const float* mW0 = (const float*)d_in[2];
    const float* mb0 = (const float*)d_in[3];
    const float* mW1 = (const float*)d_in[4];
    const float* mb1 = (const float*)d_in[5];
    const float* mW2 = (const float*)d_in[6];
    const float* mb2 = (const float*)d_in[7];
    const float* pW1 = (const float*)d_in[8];
    const float* pb1 = (const float*)d_in[9];
    const float* pW2 = (const float*)d_in[10];
    const float* pb2 = (const float*)d_in[11];
    const float* pW3 = (const float*)d_in[12];
    const float* pb3 = (const float*)d_in[13];
    float* out = (float*)d_out;

    prep_kernel<<<1, 352>>>(mW0, mb0, mW1, mb1, mW2, mb2,
                            pW1, pb1, pW2, pb2, pW3, pb3);

    // stage -> constant bank (device-to-device, graph-capturable)
    void* stage_ptr = nullptr;
    cudaGetSymbolAddress(&stage_ptr, g_stage);
    cudaMemcpyToSymbolAsync(cw2, stage_ptr, SM_N * sizeof(u64), 0,
                            cudaMemcpyDeviceToDevice);

    const int nblocks = NPTS / 2 / TPB;   // 8192
    odefunc_kernel<<<nblocks, TPB>>>(x, out);
}